// round 1
// baseline (speedup 1.0000x reference)
#include <cuda_runtime.h>

#define N_NODES 50000
#define N_EDGES 800000

// Fused-weight scratch (no allocation allowed -> __device__ globals)
__device__ float g_Wc[96 * 64];        // rows 0..63: W1[64:128]@W2a (for e_h), rows 64..95: W2[64:96] (for ext)
__device__ float g_AD[64 * 128];       // cols 0..63: A = W1[0:64]@W2a, cols 64..127: D = W1[128:192]@W2a
__device__ float g_bias[64];           // b1@W2a + b2
__device__ float g_PQ[(size_t)N_NODES * 128];  // per-node: P (cols 0..63), Q (cols 64..127)

// ---------------------------------------------------------------------------
// Kernel 1: fuse weights.  W12 = W1 @ W2[:64], route pieces into g_AD / g_Wc.
// ---------------------------------------------------------------------------
__global__ void prep_kernel(const float* __restrict__ W1, const float* __restrict__ b1,
                            const float* __restrict__ W2, const float* __restrict__ b2) {
    __shared__ float W2s[64 * 64];
    int t = threadIdx.x;
    for (int i = t; i < 64 * 64; i += blockDim.x) W2s[i] = W2[i];
    __syncthreads();

    for (int o = t; o < 192 * 64; o += blockDim.x) {
        int i = o >> 6;
        int j = o & 63;
        float s = 0.f;
#pragma unroll 8
        for (int k = 0; k < 64; k++) s = fmaf(W1[i * 64 + k], W2s[k * 64 + j], s);
        if (i < 64)       g_AD[i * 128 + j] = s;                 // A
        else if (i < 128) g_Wc[(i - 64) * 64 + j] = s;           // B
        else              g_AD[(i - 128) * 128 + 64 + j] = s;    // D
    }
    // ext weight block: W2 rows 64..95 copied verbatim
    for (int o = t; o < 32 * 64; o += blockDim.x) g_Wc[64 * 64 + o] = W2[64 * 64 + o];

    if (t < 64) {
        float s = b2[t];
#pragma unroll 8
        for (int k = 0; k < 64; k++) s = fmaf(b1[k], W2s[k * 64 + t], s);
        g_bias[t] = s;
    }
}

// ---------------------------------------------------------------------------
// Kernel 2: per-node projections  PQ[n] = [ h[n]@A , h[n]@D ]   (50000 x 128)
// Tile: 64 nodes x 128 outputs per block, K=64.  Each thread: 4 rows x 8 cols.
// ---------------------------------------------------------------------------
__global__ void __launch_bounds__(256) node_kernel(const float* __restrict__ h) {
    __shared__ float ADs[64 * 128];   // 32 KB
    __shared__ float Hs[64 * 64];     // 16 KB
    int t = threadIdx.x;

    for (int i = t; i < (64 * 128) / 4; i += 256)
        ((float4*)ADs)[i] = ((const float4*)g_AD)[i];

    int n0 = blockIdx.x * 64;
    for (int i = t; i < 1024; i += 256) {
        int m = i >> 4;
        int k4 = (i & 15) << 2;
        int n = n0 + m;
        float4 v = make_float4(0.f, 0.f, 0.f, 0.f);
        if (n < N_NODES) v = *(const float4*)(h + (size_t)n * 64 + k4);
        *(float4*)(Hs + m * 64 + k4) = v;
    }
    __syncthreads();

    int r4 = (t >> 4) << 2;   // 16 row groups of 4
    int c8 = (t & 15) << 3;   // 16 col groups of 8

    float acc[4][8];
#pragma unroll
    for (int i = 0; i < 4; i++)
#pragma unroll
        for (int j = 0; j < 8; j++) acc[i][j] = 0.f;

#pragma unroll 2
    for (int k4 = 0; k4 < 64; k4 += 4) {
        float4 a[4];
#pragma unroll
        for (int i = 0; i < 4; i++) a[i] = *(const float4*)(Hs + (r4 + i) * 64 + k4);
        float4 b[4][2];
#pragma unroll
        for (int kk = 0; kk < 4; kk++) {
            b[kk][0] = *(const float4*)(ADs + (k4 + kk) * 128 + c8);
            b[kk][1] = *(const float4*)(ADs + (k4 + kk) * 128 + c8 + 4);
        }
#pragma unroll
        for (int i = 0; i < 4; i++) {
            float av[4] = {a[i].x, a[i].y, a[i].z, a[i].w};
#pragma unroll
            for (int kk = 0; kk < 4; kk++) {
                acc[i][0] = fmaf(av[kk], b[kk][0].x, acc[i][0]);
                acc[i][1] = fmaf(av[kk], b[kk][0].y, acc[i][1]);
                acc[i][2] = fmaf(av[kk], b[kk][0].z, acc[i][2]);
                acc[i][3] = fmaf(av[kk], b[kk][0].w, acc[i][3]);
                acc[i][4] = fmaf(av[kk], b[kk][1].x, acc[i][4]);
                acc[i][5] = fmaf(av[kk], b[kk][1].y, acc[i][5]);
                acc[i][6] = fmaf(av[kk], b[kk][1].z, acc[i][6]);
                acc[i][7] = fmaf(av[kk], b[kk][1].w, acc[i][7]);
            }
        }
    }

#pragma unroll
    for (int i = 0; i < 4; i++) {
        int n = n0 + r4 + i;
        if (n < N_NODES) {
            float4 v0 = make_float4(acc[i][0], acc[i][1], acc[i][2], acc[i][3]);
            float4 v1 = make_float4(acc[i][4], acc[i][5], acc[i][6], acc[i][7]);
            *(float4*)(g_PQ + (size_t)n * 128 + c8) = v0;
            *(float4*)(g_PQ + (size_t)n * 128 + c8 + 4) = v1;
        }
    }
}

// ---------------------------------------------------------------------------
// Kernel 3: edge GEMM  [64 edges x 96] @ [96 x 64]  + gather epilogue + ReLU.
// Weights stay in SMEM across a grid-stride loop over edge tiles.
// Each thread: 4 edges x 4 outputs.
// ---------------------------------------------------------------------------
__global__ void __launch_bounds__(256) edge_kernel(
    const float* __restrict__ e_h, const float* __restrict__ ext,
    const int* __restrict__ src, const int* __restrict__ dst,
    float* __restrict__ out)
{
    __shared__ float Ws[96 * 64];   // 24 KB, loaded once per block
    __shared__ float Es[64 * 96];   // 24 KB, edge-feature tile [m][k]
    int t = threadIdx.x;

    for (int i = t; i < (96 * 64) / 4; i += 256)
        ((float4*)Ws)[i] = ((const float4*)g_Wc)[i];

    int r4 = (t >> 4) << 2;   // edge-row group
    int c4 = (t & 15) << 2;   // output-col group
    float4 bias = *(const float4*)(g_bias + c4);

    const int ntiles = N_EDGES / 64;   // 12500, exact
    for (int tile = blockIdx.x; tile < ntiles; tile += gridDim.x) {
        int e0 = tile << 6;
        __syncthreads();   // Ws ready (first iter) / Es free (later iters)

        // stage e_h -> Es[m][0..63]   (coalesced gmem, conflict-free STS.128)
#pragma unroll
        for (int i = t; i < 1024; i += 256) {
            int m = i >> 4;
            int k4 = (i & 15) << 2;
            float4 v = *(const float4*)(e_h + (size_t)(e0 + m) * 64 + k4);
            *(float4*)(Es + m * 96 + k4) = v;
        }
        // stage ext -> Es[m][64..95]
#pragma unroll
        for (int i = t; i < 512; i += 256) {
            int m = i >> 3;
            int k4 = (i & 7) << 2;
            float4 v = *(const float4*)(ext + (size_t)(e0 + m) * 32 + k4);
            *(float4*)(Es + m * 96 + 64 + k4) = v;
        }
        __syncthreads();

        float acc[4][4];
#pragma unroll
        for (int i = 0; i < 4; i++)
#pragma unroll
            for (int j = 0; j < 4; j++) acc[i][j] = 0.f;

#pragma unroll 4
        for (int k4 = 0; k4 < 96; k4 += 4) {
            float4 a[4];
#pragma unroll
            for (int i = 0; i < 4; i++) a[i] = *(const float4*)(Es + (r4 + i) * 96 + k4);
            float4 b[4];
#pragma unroll
            for (int kk = 0; kk < 4; kk++) b[kk] = *(const float4*)(Ws + (k4 + kk) * 64 + c4);
#pragma unroll
            for (int i = 0; i < 4; i++) {
                float av[4] = {a[i].x, a[i].y, a[i].z, a[i].w};
#pragma unroll
                for (int kk = 0; kk < 4; kk++) {
                    acc[i][0] = fmaf(av[kk], b[kk].x, acc[i][0]);
                    acc[i][1] = fmaf(av[kk], b[kk].y, acc[i][1]);
                    acc[i][2] = fmaf(av[kk], b[kk].z, acc[i][2]);
                    acc[i][3] = fmaf(av[kk], b[kk].w, acc[i][3]);
                }
            }
        }

        // epilogue: + P[src] + Q[dst] + bias, ReLU, store
#pragma unroll
        for (int i = 0; i < 4; i++) {
            int e = e0 + r4 + i;
            int s = src[e];
            int d = dst[e];
            float4 p = *(const float4*)(g_PQ + (size_t)s * 128 + c4);
            float4 q = *(const float4*)(g_PQ + (size_t)d * 128 + 64 + c4);
            float4 r;
            r.x = fmaxf(acc[i][0] + p.x + q.x + bias.x, 0.f);
            r.y = fmaxf(acc[i][1] + p.y + q.y + bias.y, 0.f);
            r.z = fmaxf(acc[i][2] + p.z + q.z + bias.z, 0.f);
            r.w = fmaxf(acc[i][3] + p.w + q.w + bias.w, 0.f);
            *(float4*)(out + (size_t)e * 64 + c4) = r;
        }
    }
}

// ---------------------------------------------------------------------------
extern "C" void kernel_launch(void* const* d_in, const int* in_sizes, int n_in,
                              void* d_out, int out_size) {
    const float* h   = (const float*)d_in[0];
    const float* e_h = (const float*)d_in[1];
    const float* ext = (const float*)d_in[2];
    const float* W1  = (const float*)d_in[3];
    const float* b1  = (const float*)d_in[4];
    const float* W2  = (const float*)d_in[5];
    const float* b2  = (const float*)d_in[6];
    const int*   src = (const int*)d_in[7];
    const int*   dst = (const int*)d_in[8];
    float* out = (float*)d_out;

    prep_kernel<<<1, 256>>>(W1, b1, W2, b2);
    node_kernel<<<(N_NODES + 63) / 64, 256>>>(h);
    edge_kernel<<<592, 256>>>(e_h, ext, src, dst, out);
}

// round 2
// speedup vs baseline: 1.0258x; 1.0258x over previous
#include <cuda_runtime.h>

#define N_NODES 50000
#define N_EDGES 800000

// Fused-weight scratch (no allocation allowed -> __device__ globals)
__device__ float g_Wc[96 * 64];        // rows 0..63: W1[64:128]@W2a (e_h), rows 64..95: W2[64:96] (ext)
__device__ float g_AD[64 * 128];       // cols 0..63: A = W1[0:64]@W2a, cols 64..127: D = W1[128:192]@W2a
__device__ float g_bias[64];           // b1@W2a + b2
__device__ float g_PQ[(size_t)N_NODES * 128];  // per-node: P (cols 0..63), Q (cols 64..127)

// ---- packed fp32x2 helpers (Blackwell FFMA2: 2 fp32 FMAs per issue) -------
__device__ __forceinline__ unsigned long long fma2(unsigned long long a,
                                                   unsigned long long b,
                                                   unsigned long long c) {
    unsigned long long d;
    asm("fma.rn.f32x2 %0, %1, %2, %3;" : "=l"(d) : "l"(a), "l"(b), "l"(c));
    return d;
}
__device__ __forceinline__ unsigned long long bcast2(float x) {
    unsigned long long d;
    asm("mov.b64 %0, {%1, %1};" : "=l"(d) : "r"(__float_as_uint(x)));
    return d;
}
__device__ __forceinline__ float2 unpack2(unsigned long long v) {
    unsigned int lo, hi;
    asm("mov.b64 {%0, %1}, %2;" : "=r"(lo), "=r"(hi) : "l"(v));
    return make_float2(__uint_as_float(lo), __uint_as_float(hi));
}

// ---------------------------------------------------------------------------
// Kernel 1: fuse weights.  W12 = W1 @ W2[:64], route pieces into g_AD / g_Wc.
// Parallel across 16 blocks (was 1 block = 101us).
// ---------------------------------------------------------------------------
__global__ void __launch_bounds__(256) prep_kernel(
    const float* __restrict__ W1, const float* __restrict__ b1,
    const float* __restrict__ W2, const float* __restrict__ b2) {
    __shared__ float W2s[64 * 64];
    int t = threadIdx.x;
    for (int i = t; i < 64 * 64; i += 256) W2s[i] = W2[i];
    __syncthreads();

    for (int o = blockIdx.x * 256 + t; o < 192 * 64; o += gridDim.x * 256) {
        int i = o >> 6;
        int j = o & 63;
        float s = 0.f;
#pragma unroll 8
        for (int k = 0; k < 64; k++) s = fmaf(W1[i * 64 + k], W2s[k * 64 + j], s);
        if (i < 64)       g_AD[i * 128 + j] = s;                 // A
        else if (i < 128) g_Wc[(i - 64) * 64 + j] = s;           // B
        else              g_AD[(i - 128) * 128 + 64 + j] = s;    // D
    }
    if (blockIdx.x == 0) {
        // ext weight block: W2 rows 64..95 copied verbatim
        for (int o = t; o < 32 * 64; o += 256) g_Wc[64 * 64 + o] = W2[64 * 64 + o];
        if (t < 64) {
            float s = b2[t];
#pragma unroll 8
            for (int k = 0; k < 64; k++) s = fmaf(b1[k], W2s[k * 64 + t], s);
            g_bias[t] = s;
        }
    }
}

// ---------------------------------------------------------------------------
// Kernel 2: per-node projections  PQ[n] = [ h[n]@A , h[n]@D ]   (50000 x 128)
// Tile: 64 nodes x 128 outputs per block, K=64.  Each thread: 4 rows x 8 cols.
// fp32x2-packed accumulators (4 FMA2 per (row,k) instead of 8 FFMA).
// ---------------------------------------------------------------------------
__global__ void __launch_bounds__(256) node_kernel(const float* __restrict__ h) {
    __shared__ float ADs[64 * 128];   // 32 KB
    __shared__ float Hs[64 * 64];     // 16 KB
    int t = threadIdx.x;

    for (int i = t; i < (64 * 128) / 4; i += 256)
        ((float4*)ADs)[i] = ((const float4*)g_AD)[i];

    int n0 = blockIdx.x * 64;
    for (int i = t; i < 1024; i += 256) {
        int m = i >> 4;
        int k4 = (i & 15) << 2;
        int n = n0 + m;
        float4 v = make_float4(0.f, 0.f, 0.f, 0.f);
        if (n < N_NODES) v = *(const float4*)(h + (size_t)n * 64 + k4);
        *(float4*)(Hs + m * 64 + k4) = v;
    }
    __syncthreads();

    int r4 = (t >> 4) << 2;   // 16 row groups of 4
    int c8 = (t & 15) << 3;   // 16 col groups of 8

    unsigned long long acc[4][4];
#pragma unroll
    for (int i = 0; i < 4; i++)
#pragma unroll
        for (int j = 0; j < 4; j++) acc[i][j] = 0ULL;

#pragma unroll 2
    for (int k4 = 0; k4 < 64; k4 += 4) {
        float4 a[4];
#pragma unroll
        for (int i = 0; i < 4; i++) a[i] = *(const float4*)(Hs + (r4 + i) * 64 + k4);
        ulonglong2 b[4][2];
#pragma unroll
        for (int kk = 0; kk < 4; kk++) {
            b[kk][0] = *(const ulonglong2*)(ADs + (k4 + kk) * 128 + c8);
            b[kk][1] = *(const ulonglong2*)(ADs + (k4 + kk) * 128 + c8 + 4);
        }
#pragma unroll
        for (int i = 0; i < 4; i++) {
            float av[4] = {a[i].x, a[i].y, a[i].z, a[i].w};
#pragma unroll
            for (int kk = 0; kk < 4; kk++) {
                unsigned long long ap = bcast2(av[kk]);
                acc[i][0] = fma2(ap, b[kk][0].x, acc[i][0]);
                acc[i][1] = fma2(ap, b[kk][0].y, acc[i][1]);
                acc[i][2] = fma2(ap, b[kk][1].x, acc[i][2]);
                acc[i][3] = fma2(ap, b[kk][1].y, acc[i][3]);
            }
        }
    }

#pragma unroll
    for (int i = 0; i < 4; i++) {
        int n = n0 + r4 + i;
        if (n < N_NODES) {
            float2 v0 = unpack2(acc[i][0]), v1 = unpack2(acc[i][1]);
            float2 v2 = unpack2(acc[i][2]), v3 = unpack2(acc[i][3]);
            *(float4*)(g_PQ + (size_t)n * 128 + c8)     = make_float4(v0.x, v0.y, v1.x, v1.y);
            *(float4*)(g_PQ + (size_t)n * 128 + c8 + 4) = make_float4(v2.x, v2.y, v3.x, v3.y);
        }
    }
}

// ---------------------------------------------------------------------------
// Kernel 3: edge GEMM  [64 edges x 96] @ [96 x 64]  + gather epilogue + ReLU.
// Weights stay in SMEM across a grid-stride loop over edge tiles.
// Each thread: 4 edges x 4 outputs, fp32x2-packed (2 FMA2 per (edge,k)).
// ---------------------------------------------------------------------------
__global__ void __launch_bounds__(256) edge_kernel(
    const float* __restrict__ e_h, const float* __restrict__ ext,
    const int* __restrict__ src, const int* __restrict__ dst,
    float* __restrict__ out)
{
    __shared__ float Ws[96 * 64];   // 24 KB, loaded once per block
    __shared__ float Es[64 * 96];   // 24 KB, edge-feature tile [m][k]
    int t = threadIdx.x;

    for (int i = t; i < (96 * 64) / 4; i += 256)
        ((float4*)Ws)[i] = ((const float4*)g_Wc)[i];

    int r4 = (t >> 4) << 2;   // edge-row group
    int c4 = (t & 15) << 2;   // output-col group
    float4 bias = *(const float4*)(g_bias + c4);

    const int ntiles = N_EDGES / 64;   // 12500, exact
    for (int tile = blockIdx.x; tile < ntiles; tile += gridDim.x) {
        int e0 = tile << 6;
        __syncthreads();   // Ws ready (first iter) / Es free (later iters)

        // stage e_h -> Es[m][0..63]
#pragma unroll
        for (int i = t; i < 1024; i += 256) {
            int m = i >> 4;
            int k4 = (i & 15) << 2;
            float4 v = *(const float4*)(e_h + (size_t)(e0 + m) * 64 + k4);
            *(float4*)(Es + m * 96 + k4) = v;
        }
        // stage ext -> Es[m][64..95]
#pragma unroll
        for (int i = t; i < 512; i += 256) {
            int m = i >> 3;
            int k4 = (i & 7) << 2;
            float4 v = *(const float4*)(ext + (size_t)(e0 + m) * 32 + k4);
            *(float4*)(Es + m * 96 + 64 + k4) = v;
        }
        __syncthreads();

        unsigned long long acc[4][2];
#pragma unroll
        for (int i = 0; i < 4; i++) { acc[i][0] = 0ULL; acc[i][1] = 0ULL; }

#pragma unroll 4
        for (int k4 = 0; k4 < 96; k4 += 4) {
            float4 a[4];
#pragma unroll
            for (int i = 0; i < 4; i++) a[i] = *(const float4*)(Es + (r4 + i) * 96 + k4);
            ulonglong2 b[4];
#pragma unroll
            for (int kk = 0; kk < 4; kk++) b[kk] = *(const ulonglong2*)(Ws + (k4 + kk) * 64 + c4);
#pragma unroll
            for (int i = 0; i < 4; i++) {
                float av[4] = {a[i].x, a[i].y, a[i].z, a[i].w};
#pragma unroll
                for (int kk = 0; kk < 4; kk++) {
                    unsigned long long ap = bcast2(av[kk]);
                    acc[i][0] = fma2(ap, b[kk].x, acc[i][0]);
                    acc[i][1] = fma2(ap, b[kk].y, acc[i][1]);
                }
            }
        }

        // epilogue: + P[src] + Q[dst] + bias, ReLU, store
#pragma unroll
        for (int i = 0; i < 4; i++) {
            int e = e0 + r4 + i;
            int s = src[e];
            int d = dst[e];
            float4 p = *(const float4*)(g_PQ + (size_t)s * 128 + c4);
            float4 q = *(const float4*)(g_PQ + (size_t)d * 128 + 64 + c4);
            float2 lo = unpack2(acc[i][0]);
            float2 hi = unpack2(acc[i][1]);
            float4 r;
            r.x = fmaxf(lo.x + p.x + q.x + bias.x, 0.f);
            r.y = fmaxf(lo.y + p.y + q.y + bias.y, 0.f);
            r.z = fmaxf(hi.x + p.z + q.z + bias.z, 0.f);
            r.w = fmaxf(hi.y + p.w + q.w + bias.w, 0.f);
            *(float4*)(out + (size_t)e * 64 + c4) = r;
        }
    }
}

// ---------------------------------------------------------------------------
extern "C" void kernel_launch(void* const* d_in, const int* in_sizes, int n_in,
                              void* d_out, int out_size) {
    const float* h   = (const float*)d_in[0];
    const float* e_h = (const float*)d_in[1];
    const float* ext = (const float*)d_in[2];
    const float* W1  = (const float*)d_in[3];
    const float* b1  = (const float*)d_in[4];
    const float* W2  = (const float*)d_in[5];
    const float* b2  = (const float*)d_in[6];
    const int*   src = (const int*)d_in[7];
    const int*   dst = (const int*)d_in[8];
    float* out = (float*)d_out;

    prep_kernel<<<16, 256>>>(W1, b1, W2, b2);
    node_kernel<<<(N_NODES + 63) / 64, 256>>>(h);
    edge_kernel<<<592, 256>>>(e_h, ext, src, dst, out);
}

// round 4
// speedup vs baseline: 1.6329x; 1.5918x over previous
#include <cuda_runtime.h>
#include <cstdint>

#define N_NODES 50000
#define N_EDGES 800000

// ---- fused-weight / node-projection scratch (__device__ globals; no alloc) ----
__device__ float g_Wc[96 * 64];        // [k][n]: rows 0..63 = W1[64:128]@W2a, rows 64..95 = W2[64:96]
__device__ float g_AD[64 * 128];       // cols 0..63: A = W1[0:64]@W2a, cols 64..127: D = W1[128:192]@W2a
__device__ float g_bias[64];           // b1@W2a + b2
__device__ float g_PQ[(size_t)N_NODES * 128];  // per-node: P (cols 0..63), Q (cols 64..127)

__device__ __forceinline__ uint32_t f2tf32(float x) {
    uint32_t r;
    asm("cvt.rna.tf32.f32 %0, %1;" : "=r"(r) : "f"(x));
    return r;
}

// ---------------------------------------------------------------------------
// Kernel 1: fuse weights. 48 blocks x 256 thr, one output per thread.
// ---------------------------------------------------------------------------
__global__ void __launch_bounds__(256) prep_kernel(
    const float* __restrict__ W1, const float* __restrict__ b1,
    const float* __restrict__ W2, const float* __restrict__ b2) {
    __shared__ float W2s[64 * 64];
    int t = threadIdx.x;
    for (int i = t; i < 64 * 64; i += 256) W2s[i] = W2[i];
    __syncthreads();

    int o = blockIdx.x * 256 + t;   // 48*256 = 12288 = 192*64 exactly
    {
        int i = o >> 6;
        int j = o & 63;
        float s = 0.f;
#pragma unroll 8
        for (int k = 0; k < 64; k++) s = fmaf(W1[i * 64 + k], W2s[k * 64 + j], s);
        if (i < 64)       g_AD[i * 128 + j] = s;                 // A
        else if (i < 128) g_Wc[(i - 64) * 64 + j] = s;           // B (e_h block)
        else              g_AD[(i - 128) * 128 + 64 + j] = s;    // D
    }
    if (blockIdx.x == 0) {
        for (int i = t; i < 32 * 64; i += 256) g_Wc[64 * 64 + i] = W2[64 * 64 + i];  // ext block
        if (t < 64) {
            float s = b2[t];
#pragma unroll 8
            for (int k = 0; k < 64; k++) s = fmaf(b1[k], W2s[k * 64 + t], s);
            g_bias[t] = s;
        }
    }
}

// ---------------------------------------------------------------------------
// Kernel 2: per-node projections  PQ[n] = [ h[n]@A , h[n]@D ]  (fp32 SIMT)
// ---------------------------------------------------------------------------
__global__ void __launch_bounds__(256) node_kernel(const float* __restrict__ h) {
    __shared__ float ADs[64 * 128];
    __shared__ float Hs[64 * 64];
    int t = threadIdx.x;

    for (int i = t; i < (64 * 128) / 4; i += 256)
        ((float4*)ADs)[i] = ((const float4*)g_AD)[i];

    int n0 = blockIdx.x * 64;
    for (int i = t; i < 1024; i += 256) {
        int m = i >> 4;
        int k4 = (i & 15) << 2;
        int n = n0 + m;
        float4 v = make_float4(0.f, 0.f, 0.f, 0.f);
        if (n < N_NODES) v = *(const float4*)(h + (size_t)n * 64 + k4);
        *(float4*)(Hs + m * 64 + k4) = v;
    }
    __syncthreads();

    int r4 = (t >> 4) << 2;
    int c8 = (t & 15) << 3;

    float acc[4][8];
#pragma unroll
    for (int i = 0; i < 4; i++)
#pragma unroll
        for (int j = 0; j < 8; j++) acc[i][j] = 0.f;

#pragma unroll 2
    for (int k4 = 0; k4 < 64; k4 += 4) {
        float4 a[4];
#pragma unroll
        for (int i = 0; i < 4; i++) a[i] = *(const float4*)(Hs + (r4 + i) * 64 + k4);
        float4 b[4][2];
#pragma unroll
        for (int kk = 0; kk < 4; kk++) {
            b[kk][0] = *(const float4*)(ADs + (k4 + kk) * 128 + c8);
            b[kk][1] = *(const float4*)(ADs + (k4 + kk) * 128 + c8 + 4);
        }
#pragma unroll
        for (int i = 0; i < 4; i++) {
            float av[4] = {a[i].x, a[i].y, a[i].z, a[i].w};
#pragma unroll
            for (int kk = 0; kk < 4; kk++) {
                acc[i][0] = fmaf(av[kk], b[kk][0].x, acc[i][0]);
                acc[i][1] = fmaf(av[kk], b[kk][0].y, acc[i][1]);
                acc[i][2] = fmaf(av[kk], b[kk][0].z, acc[i][2]);
                acc[i][3] = fmaf(av[kk], b[kk][0].w, acc[i][3]);
                acc[i][4] = fmaf(av[kk], b[kk][1].x, acc[i][4]);
                acc[i][5] = fmaf(av[kk], b[kk][1].y, acc[i][5]);
                acc[i][6] = fmaf(av[kk], b[kk][1].z, acc[i][6]);
                acc[i][7] = fmaf(av[kk], b[kk][1].w, acc[i][7]);
            }
        }
    }

#pragma unroll
    for (int i = 0; i < 4; i++) {
        int n = n0 + r4 + i;
        if (n < N_NODES) {
            *(float4*)(g_PQ + (size_t)n * 128 + c8) =
                make_float4(acc[i][0], acc[i][1], acc[i][2], acc[i][3]);
            *(float4*)(g_PQ + (size_t)n * 128 + c8 + 4) =
                make_float4(acc[i][4], acc[i][5], acc[i][6], acc[i][7]);
        }
    }
}

// ---------------------------------------------------------------------------
// Kernel 3: tf32 mma.sync edge GEMM.  Tile: [128 edges x 96] @ [96 x 64]
// 8 warps = 4 M-groups (32 rows) x 2 N-groups (32 cols).
// Warp: 2 mfrags x 4 nfrags of m16n8k8, 12 K-steps. Epilogue: +P[src]+Q[dst]+bias, ReLU.
// ---------------------------------------------------------------------------
#define TILE_M 128
#define NTILES (N_EDGES / TILE_M)       // 6250
#define EDGE_GRID 296                   // 148 SMs x 2 CTAs

#define A_STRIDE 100                    // floats; bank = (4*row + col) % 32 -> conflict-free frags
#define B_STRIDE 72                     // floats; bank = (8*k + n) % 32 -> conflict-free frags
#define SMEM_A_OFF 0
#define SMEM_B_OFF (TILE_M * A_STRIDE)             // 12800 words
#define SMEM_BIAS_OFF (SMEM_B_OFF + 96 * B_STRIDE) // 19712 words
#define SMEM_WORDS (SMEM_BIAS_OFF + 64)            // 19776 words = 79104 B

__device__ __forceinline__ void mma_tf32(float c[4], const uint32_t a[4], const uint32_t b[2]) {
    asm volatile(
        "mma.sync.aligned.m16n8k8.row.col.f32.tf32.tf32.f32 "
        "{%0,%1,%2,%3}, {%4,%5,%6,%7}, {%8,%9}, {%0,%1,%2,%3};"
        : "+f"(c[0]), "+f"(c[1]), "+f"(c[2]), "+f"(c[3])
        : "r"(a[0]), "r"(a[1]), "r"(a[2]), "r"(a[3]), "r"(b[0]), "r"(b[1]));
}

__global__ void __launch_bounds__(256, 2) edge_kernel(
    const float* __restrict__ e_h, const float* __restrict__ ext,
    const int* __restrict__ src, const int* __restrict__ dst,
    float* __restrict__ out)
{
    extern __shared__ uint32_t smw[];
    uint32_t* As = smw + SMEM_A_OFF;
    uint32_t* Bs = smw + SMEM_B_OFF;
    float*  bias = (float*)(smw + SMEM_BIAS_OFF);

    int t = threadIdx.x;
    int wid = t >> 5;
    int lane = t & 31;
    int mw = wid >> 1;        // 0..3 -> M rows [mw*32, mw*32+32)
    int nw = wid & 1;         // 0..1 -> N cols [nw*32, nw*32+32)
    int lq = lane >> 2;       // 0..7
    int lr = lane & 3;        // 0..3

    // stage B (weights, tf32, [k][n] stride 72) + bias — once per CTA
    for (int i = t; i < 96 * 64; i += 256) {
        int k = i >> 6;
        int n = i & 63;
        Bs[k * B_STRIDE + n] = f2tf32(g_Wc[i]);
    }
    if (t < 64) bias[t] = g_bias[t];

    for (int tile = blockIdx.x; tile < NTILES; tile += EDGE_GRID) {
        int e0 = tile * TILE_M;
        __syncthreads();   // prev-iter LDS of As done (first iter: B/bias visible)

        // ---- stage A: e_h -> cols 0..63 (cvt to tf32) ----
#pragma unroll
        for (int i = t; i < 2048; i += 256) {
            int m = i >> 4;
            int c4 = (i & 15) << 2;
            float4 v = *(const float4*)(e_h + (size_t)(e0 + m) * 64 + c4);
            uint4 w = make_uint4(f2tf32(v.x), f2tf32(v.y), f2tf32(v.z), f2tf32(v.w));
            *(uint4*)(As + m * A_STRIDE + c4) = w;
        }
        // ---- stage A: ext -> cols 64..95 ----
#pragma unroll
        for (int i = t; i < 1024; i += 256) {
            int m = i >> 3;
            int c4 = (i & 7) << 2;
            float4 v = *(const float4*)(ext + (size_t)(e0 + m) * 32 + c4);
            uint4 w = make_uint4(f2tf32(v.x), f2tf32(v.y), f2tf32(v.z), f2tf32(v.w));
            *(uint4*)(As + m * A_STRIDE + 64 + c4) = w;
        }
        __syncthreads();

        // ---- mma mainloop: 12 K-steps of 8 ----
        float c[2][4][4];
#pragma unroll
        for (int mf = 0; mf < 2; mf++)
#pragma unroll
            for (int nf = 0; nf < 4; nf++)
#pragma unroll
                for (int i = 0; i < 4; i++) c[mf][nf][i] = 0.f;

#pragma unroll
        for (int ks = 0; ks < 12; ks++) {
            int kb = ks * 8;
            uint32_t a[2][4];
#pragma unroll
            for (int mf = 0; mf < 2; mf++) {
                const uint32_t* ap = As + (mw * 32 + mf * 16 + lq) * A_STRIDE + kb + lr;
                a[mf][0] = ap[0];
                a[mf][1] = ap[8 * A_STRIDE];
                a[mf][2] = ap[4];
                a[mf][3] = ap[8 * A_STRIDE + 4];
            }
            uint32_t b[4][2];
#pragma unroll
            for (int nf = 0; nf < 4; nf++) {
                const uint32_t* bp = Bs + (kb + lr) * B_STRIDE + nw * 32 + nf * 8 + lq;
                b[nf][0] = bp[0];
                b[nf][1] = bp[4 * B_STRIDE];
            }
#pragma unroll
            for (int mf = 0; mf < 2; mf++)
#pragma unroll
                for (int nf = 0; nf < 4; nf++)
                    mma_tf32(c[mf][nf], a[mf], b[nf]);
        }

        // ---- epilogue: +P[src] +Q[dst] +bias, ReLU, store (float2 lanes) ----
#pragma unroll
        for (int mf = 0; mf < 2; mf++) {
#pragma unroll
            for (int half = 0; half < 2; half++) {
                int r = mw * 32 + mf * 16 + half * 8 + lq;
                int e = e0 + r;
                int s = src[e];
                int d = dst[e];
                const float* P = g_PQ + (size_t)s * 128;
                const float* Q = g_PQ + (size_t)d * 128 + 64;
#pragma unroll
                for (int nf = 0; nf < 4; nf++) {
                    int col = nw * 32 + nf * 8 + 2 * lr;
                    float2 p = *(const float2*)(P + col);
                    float2 q = *(const float2*)(Q + col);
                    float2 bv = *(const float2*)(bias + col);
                    float cx = c[mf][nf][half * 2 + 0];
                    float cy = c[mf][nf][half * 2 + 1];
                    float2 rv;
                    rv.x = fmaxf(cx + p.x + q.x + bv.x, 0.f);
                    rv.y = fmaxf(cy + p.y + q.y + bv.y, 0.f);
                    *(float2*)(out + (size_t)e * 64 + col) = rv;
                }
            }
        }
    }
}

// ---------------------------------------------------------------------------
extern "C" void kernel_launch(void* const* d_in, const int* in_sizes, int n_in,
                              void* d_out, int out_size) {
    const float* h   = (const float*)d_in[0];
    const float* e_h = (const float*)d_in[1];
    const float* ext = (const float*)d_in[2];
    const float* W1  = (const float*)d_in[3];
    const float* b1  = (const float*)d_in[4];
    const float* W2  = (const float*)d_in[5];
    const float* b2  = (const float*)d_in[6];
    const int*   src = (const int*)d_in[7];
    const int*   dst = (const int*)d_in[8];
    float* out = (float*)d_out;

    static bool attr_set = false;
    if (!attr_set) {
        cudaFuncSetAttribute(edge_kernel, cudaFuncAttributeMaxDynamicSharedMemorySize,
                             SMEM_WORDS * 4);
        attr_set = true;
    }

    prep_kernel<<<48, 256>>>(W1, b1, W2, b2);
    node_kernel<<<(N_NODES + 63) / 64, 256>>>(h);
    edge_kernel<<<EDGE_GRID, 256, SMEM_WORDS * 4>>>(e_h, ext, src, dst, out);
}